// round 3
// baseline (speedup 1.0000x reference)
#include <cuda_runtime.h>
#include <cstdint>

#define EMA_OLD 0.01f
#define EMA_NEW 0.99f

#define MAXB 4096
#define MAXN 1024

// Scratch (allocation-free rule: __device__ globals)
__device__ unsigned long long g_best[MAXB];   // packed (sortable_score << 32) | j
__device__ int                g_winner[MAXN]; // max b with z[b]==j, or -1
__device__ float              g_mnorm[MAXN];  // ||m_j||^2

// ---------------------------------------------------------------------------
__global__ void init_kernel(int B, int n) {
    int i = blockIdx.x * blockDim.x + threadIdx.x;
    if (i < B) g_best[i] = 0xFFFFFFFFFFFFFFFFull;
    if (i < n) g_winner[i] = -1;
}

// ---------------------------------------------------------------------------
__global__ void mnorm_kernel(const float* __restrict__ M, int D) {
    int j = blockIdx.x;
    const float* row = M + (size_t)j * D;
    float s = 0.f;
    for (int d = threadIdx.x; d < D; d += blockDim.x) {
        float v = row[d];
        s = fmaf(v, v, s);
    }
    __shared__ float sh[256];
    sh[threadIdx.x] = s;
    __syncthreads();
    for (int off = 128; off > 0; off >>= 1) {
        if (threadIdx.x < off) sh[threadIdx.x] += sh[threadIdx.x + off];
        __syncthreads();
    }
    if (threadIdx.x == 0) g_mnorm[j] = sh[0];
}

// ---------------------------------------------------------------------------
// Fused SGEMM (y @ m^T) + row argmin, accumulating with packed fma.rn.f32x2
// (FFMA2: 2 fp32 MACs per instruction). Tile 128x128, BK=16, 256 threads,
// 8x8 per-thread microtile with the 8 N-columns packed into 4 f32x2 lanes.
#define BM 128
#define BN 128
#define BK 16
#define TM 8
#define TN 8

__device__ __forceinline__ unsigned fkey(float f) {
    unsigned u = __float_as_uint(f);
    return (u & 0x80000000u) ? ~u : (u | 0x80000000u);  // order-preserving
}

#define FMA_F32X2(acc, a, b) \
    asm("fma.rn.f32x2 %0, %1, %2, %0;" : "+l"(acc) : "l"(a), "l"(b))

#define PACK_DUP_F32X2(out, v) \
    asm("mov.b64 %0, {%1, %1};" : "=l"(out) : "r"(__float_as_uint(v)))

__global__ __launch_bounds__(256, 2)
void gemm_argmin_kernel(const float* __restrict__ Y,
                        const float* __restrict__ M,
                        int D) {
    __shared__ float As[BK][BM + 4];
    __shared__ float Bs[BK][BN + 4];

    const int tid = threadIdx.x;
    const int tx = tid & 15;   // col group (j)
    const int ty = tid >> 4;   // row group (b)
    const int brow = blockIdx.y * BM;  // y rows
    const int bcol = blockIdx.x * BN;  // m rows (cluster j)

    // Packed accumulators: acc2[i][jp] holds columns {2jp, 2jp+1} for row i.
    unsigned long long acc2[TM][TN / 2];
#pragma unroll
    for (int i = 0; i < TM; i++)
#pragma unroll
        for (int j = 0; j < TN / 2; j++) acc2[i][j] = 0ull;

    const float* Yb = Y + (size_t)brow * D;
    const float* Mb = M + (size_t)bcol * D;

    for (int k0 = 0; k0 < D; k0 += BK) {
        // Prefetch gmem tiles into registers, then fill smem (transposed).
        float4 pa[2], pb[2];
#pragma unroll
        for (int it = 0; it < 2; it++) {
            int v = tid + it * 256;
            int row = v >> 2;
            int c4 = v & 3;
            pa[it] = *(const float4*)(Yb + (size_t)row * D + k0 + c4 * 4);
            pb[it] = *(const float4*)(Mb + (size_t)row * D + k0 + c4 * 4);
        }
        __syncthreads();  // protect smem from previous iteration's readers
#pragma unroll
        for (int it = 0; it < 2; it++) {
            int v = tid + it * 256;
            int row = v >> 2;
            int c4 = v & 3;
            As[c4 * 4 + 0][row] = pa[it].x;
            As[c4 * 4 + 1][row] = pa[it].y;
            As[c4 * 4 + 2][row] = pa[it].z;
            As[c4 * 4 + 3][row] = pa[it].w;
            Bs[c4 * 4 + 0][row] = pb[it].x;
            Bs[c4 * 4 + 1][row] = pb[it].y;
            Bs[c4 * 4 + 2][row] = pb[it].z;
            Bs[c4 * 4 + 3][row] = pb[it].w;
        }
        __syncthreads();

#pragma unroll
        for (int k = 0; k < BK; k++) {
            // B fragment: 8 floats = 4 packed f32x2 lanes (free pairing via v2.u64).
            unsigned long long bp[4];
            {
                ulonglong2 t0 = *(const ulonglong2*)&Bs[k][tx * TN];
                ulonglong2 t1 = *(const ulonglong2*)&Bs[k][tx * TN + 4];
                bp[0] = t0.x; bp[1] = t0.y; bp[2] = t1.x; bp[3] = t1.y;
            }
            // A fragment: 8 floats, each duplicated into both f32x2 halves.
            float af[TM];
#pragma unroll
            for (int i = 0; i < TM; i += 4) {
                float4 t = *(const float4*)&As[k][ty * TM + i];
                af[i] = t.x; af[i + 1] = t.y; af[i + 2] = t.z; af[i + 3] = t.w;
            }
            unsigned long long ap[TM];
#pragma unroll
            for (int i = 0; i < TM; i++) PACK_DUP_F32X2(ap[i], af[i]);

#pragma unroll
            for (int i = 0; i < TM; i++)
#pragma unroll
                for (int jp = 0; jp < TN / 2; jp++)
                    FMA_F32X2(acc2[i][jp], ap[i], bp[jp]);
        }
    }

    // Scores and fused argmin.
    float mn[TN];
#pragma unroll
    for (int j = 0; j < TN; j++) mn[j] = g_mnorm[bcol + tx * TN + j];

#pragma unroll
    for (int i = 0; i < TM; i++) {
        unsigned long long pk = 0xFFFFFFFFFFFFFFFFull;
#pragma unroll
        for (int jp = 0; jp < TN / 2; jp++) {
            unsigned lo = (unsigned)(acc2[i][jp] & 0xFFFFFFFFull);
            unsigned hi = (unsigned)(acc2[i][jp] >> 32);
            float v0 = __uint_as_float(lo);
            float v1 = __uint_as_float(hi);
            float sc0 = fmaf(-2.0f, v0, mn[2 * jp]);
            float sc1 = fmaf(-2.0f, v1, mn[2 * jp + 1]);
            unsigned long long c0 =
                ((unsigned long long)fkey(sc0) << 32) |
                (unsigned)(bcol + tx * TN + 2 * jp);
            unsigned long long c1 =
                ((unsigned long long)fkey(sc1) << 32) |
                (unsigned)(bcol + tx * TN + 2 * jp + 1);
            pk = (c0 < pk) ? c0 : pk;
            pk = (c1 < pk) ? c1 : pk;
        }
        // Reduce across the 16 tx-lanes sharing this row (xor stays in-warp).
#pragma unroll
        for (int off = 1; off < 16; off <<= 1) {
            unsigned long long o = __shfl_xor_sync(0xFFFFFFFFu, pk, off);
            pk = (o < pk) ? o : pk;
        }
        if (tx == 0)
            atomicMin(&g_best[brow + ty * TM + i], pk);
    }
}

// ---------------------------------------------------------------------------
__global__ void winner_kernel(int B) {
    int b = blockIdx.x * blockDim.x + threadIdx.x;
    if (b < B) {
        int z = (int)(g_best[b] & 0xFFFFFFFFull);
        atomicMax(&g_winner[z], b);   // last-write-wins => max b
    }
}

// ---------------------------------------------------------------------------
__global__ void output_kernel(const float* __restrict__ Y,
                              const float* __restrict__ M,
                              const float* __restrict__ SD,
                              float* __restrict__ out,
                              int D, int n) {
    int j = blockIdx.x;
    int w = g_winner[j];
    int D4 = D >> 2;
    const float4* mrow  = (const float4*)(M  + (size_t)j * D);
    const float4* sdrow = (const float4*)(SD + (size_t)j * D);
    float4* om = (float4*)(out + (size_t)j * D);
    float4* os = (float4*)(out + (size_t)(n + j) * D);

    if (w < 0) {
        for (int d = threadIdx.x; d < D4; d += blockDim.x) {
            om[d] = mrow[d];
            os[d] = sdrow[d];
        }
    } else {
        const float4* yrow = (const float4*)(Y + (size_t)w * D);
        for (int d = threadIdx.x; d < D4; d += blockDim.x) {
            float4 mv = mrow[d], yv = yrow[d], sv = sdrow[d];
            float4 nm, ns;
            nm.x = mv.x * EMA_OLD + yv.x * EMA_NEW;
            nm.y = mv.y * EMA_OLD + yv.y * EMA_NEW;
            nm.z = mv.z * EMA_OLD + yv.z * EMA_NEW;
            nm.w = mv.w * EMA_OLD + yv.w * EMA_NEW;
            float dx = nm.x - yv.x, dy = nm.y - yv.y,
                  dz = nm.z - yv.z, dw = nm.w - yv.w;
            ns.x = dx * dx * EMA_OLD + sv.x * EMA_NEW;
            ns.y = dy * dy * EMA_OLD + sv.y * EMA_NEW;
            ns.z = dz * dz * EMA_OLD + sv.z * EMA_NEW;
            ns.w = dw * dw * EMA_OLD + sv.w * EMA_NEW;
            om[d] = nm;
            os[d] = ns;
        }
    }
}

// ---------------------------------------------------------------------------
extern "C" void kernel_launch(void* const* d_in, const int* in_sizes, int n_in,
                              void* d_out, int out_size) {
    const float* y  = (const float*)d_in[0];
    const float* m  = (const float*)d_in[1];
    const float* sd = (const float*)d_in[2];
    (void)n_in; (void)out_size;

    const int n = in_sizes[3];            // 1024
    const int D = in_sizes[1] / n;        // 4096
    const int B = in_sizes[0] / D;        // 4096
    float* out = (float*)d_out;

    int initN = (B > n ? B : n);
    init_kernel<<<(initN + 255) / 256, 256>>>(B, n);
    mnorm_kernel<<<n, 256>>>(m, D);

    dim3 grid(n / BN, B / BM);
    gemm_argmin_kernel<<<grid, 256>>>(y, m, D);

    winner_kernel<<<(B + 255) / 256, 256>>>(B);
    output_kernel<<<n, 256>>>(y, m, sd, out, D, n);
}

// round 4
// speedup vs baseline: 1.4811x; 1.4811x over previous
#include <cuda_runtime.h>
#include <cstdint>

#define EMA_OLD 0.01f
#define EMA_NEW 0.99f

#define MAXB 4096
#define MAXN 1024

__device__ unsigned long long g_best[MAXB];   // packed (sortable_score << 32) | j
__device__ int                g_winner[MAXN];
__device__ float              g_mnorm[MAXN];

// ---------------------------------------------------------------------------
__global__ void init_kernel(int B, int n) {
    int i = blockIdx.x * blockDim.x + threadIdx.x;
    if (i < B) g_best[i] = 0xFFFFFFFFFFFFFFFFull;
    if (i < n) g_winner[i] = -1;
}

// ---------------------------------------------------------------------------
__global__ void mnorm_kernel(const float* __restrict__ M, int D) {
    int j = blockIdx.x;
    const float* row = M + (size_t)j * D;
    float s = 0.f;
    for (int d = threadIdx.x; d < D; d += blockDim.x) {
        float v = row[d];
        s = fmaf(v, v, s);
    }
    __shared__ float sh[256];
    sh[threadIdx.x] = s;
    __syncthreads();
    for (int off = 128; off > 0; off >>= 1) {
        if (threadIdx.x < off) sh[threadIdx.x] += sh[threadIdx.x + off];
        __syncthreads();
    }
    if (threadIdx.x == 0) g_mnorm[j] = sh[0];
}

// ===========================================================================
// 3xTF32 mma.sync GEMM (y @ m^T) fused with row argmin.
// CTA 128x128, BK=32, 256 threads = 8 warps in 4(M) x 2(N); warp tile 32x64.
// Smem: fragment-major layout, XOR-swizzled; double buffered.
// ===========================================================================
#define BM 128
#define BN 128
#define BK 32

// Offsets within one 64KB buffer
#define S_AHI 0
#define S_ALO 16384
#define S_BHI 32768
#define S_BLO 49152
#define BUF_BYTES 65536
#define S_MN  (2 * BUF_BYTES)
#define SMEM_TOT (S_MN + 512)

__device__ __forceinline__ uint32_t swzA(uint32_t b) { return b ^ ((b >> 4) & 0xF0u); }
__device__ __forceinline__ uint32_t swzB(uint32_t b) { return b ^ ((b >> 3) & 0x70u); }

__device__ __forceinline__ uint32_t smem_u32(const void* p) {
    uint32_t a;
    asm("{ .reg .u64 t; cvta.to.shared.u64 t, %1; cvt.u32.u64 %0, t; }" : "=r"(a) : "l"(p));
    return a;
}
__device__ __forceinline__ void tf32_split(float x, uint32_t& h, uint32_t& l) {
    asm("cvt.rna.tf32.f32 %0, %1;" : "=r"(h) : "f"(x));
    float r = x - __uint_as_float(h);
    asm("cvt.rna.tf32.f32 %0, %1;" : "=r"(l) : "f"(r));
}
__device__ __forceinline__ void mma8(float* d, const uint32_t* a, const uint32_t* b) {
    asm volatile(
        "mma.sync.aligned.m16n8k8.row.col.f32.tf32.tf32.f32 "
        "{%0,%1,%2,%3}, {%4,%5,%6,%7}, {%8,%9}, {%0,%1,%2,%3};"
        : "+f"(d[0]), "+f"(d[1]), "+f"(d[2]), "+f"(d[3])
        : "r"(a[0]), "r"(a[1]), "r"(a[2]), "r"(a[3]), "r"(b[0]), "r"(b[1]));
}
__device__ __forceinline__ uint32_t lds_u32(uint32_t addr) {
    uint32_t v;
    asm volatile("ld.shared.b32 %0, [%1];" : "=r"(v) : "r"(addr));
    return v;
}
__device__ __forceinline__ void sts_128(uint32_t addr, uint4 v) {
    asm volatile("st.shared.v4.b32 [%0], {%1,%2,%3,%4};"
                 :: "r"(addr), "r"(v.x), "r"(v.y), "r"(v.z), "r"(v.w));
}
__device__ __forceinline__ unsigned fkey(float f) {
    unsigned u = __float_as_uint(f);
    return (u & 0x80000000u) ? ~u : (u | 0x80000000u);
}
__device__ __forceinline__ unsigned long long umin64(unsigned long long a,
                                                     unsigned long long b) {
    return a < b ? a : b;
}

__global__ __launch_bounds__(256, 1)
void gemm_argmin_mma(const float* __restrict__ Y,
                     const float* __restrict__ M,
                     int D) {
    extern __shared__ __align__(1024) char smem[];
    const uint32_t sbase = smem_u32(smem);
    const int tid  = threadIdx.x;
    const int lane = tid & 31;
    const int wid  = tid >> 5;
    const int wm   = wid >> 1;       // 0..3 (M)
    const int wn   = wid & 1;        // 0..1 (N)
    const int brow = blockIdx.y * BM;
    const int bcol = blockIdx.x * BN;

    float* sh_mn = (float*)(smem + S_MN);
    if (tid < 128) sh_mn[tid] = g_mnorm[bcol + tid];

    // ---- producer addressing (4 float4 per tensor per chunk per thread) ----
    // iter i: row r = (tid>>3) + 32*i, col c = 4*(tid&7)
    const int prow = tid >> 3;
    const int pcol = (tid & 7) * 4;
    uint32_t offA[4], offB[4];
#pragma unroll
    for (int i = 0; i < 4; i++) {
        int r = prow + 32 * i;
        offA[i] = swzA((uint32_t)(((r >> 4) * 4 + (pcol >> 3)) * 512 +
                                  (((r >> 3) & 1) + ((pcol >> 2) & 1) * 2) * 128 +
                                  (r & 7) * 16));
        offB[i] = swzB((uint32_t)(((r >> 3) * 4 + (pcol >> 3)) * 256 +
                                  ((pcol >> 2) & 1) * 128 + (r & 7) * 16));
    }
    const float* Yp = Y + (size_t)(brow + prow) * D + pcol;
    const float* Mp = M + (size_t)(bcol + prow) * D + pcol;

    float acc[2][8][4];
#pragma unroll
    for (int mt = 0; mt < 2; mt++)
#pragma unroll
        for (int nt = 0; nt < 8; nt++)
#pragma unroll
            for (int q = 0; q < 4; q++) acc[mt][nt][q] = 0.f;

    const int NK = D / BK;
    float4 ya[4], ma[4];

    // prologue: chunk 0 -> buf 0
#pragma unroll
    for (int i = 0; i < 4; i++) {
        ya[i] = *(const float4*)(Yp + (size_t)(32 * i) * D);
        ma[i] = *(const float4*)(Mp + (size_t)(32 * i) * D);
    }
    {
        const uint32_t bb = sbase;
#pragma unroll
        for (int i = 0; i < 4; i++) {
            uint4 h, l;
            tf32_split(ya[i].x, h.x, l.x); tf32_split(ya[i].y, h.y, l.y);
            tf32_split(ya[i].z, h.z, l.z); tf32_split(ya[i].w, h.w, l.w);
            sts_128(bb + S_AHI + offA[i], h);
            sts_128(bb + S_ALO + offA[i], l);
            tf32_split(ma[i].x, h.x, l.x); tf32_split(ma[i].y, h.y, l.y);
            tf32_split(ma[i].z, h.z, l.z); tf32_split(ma[i].w, h.w, l.w);
            sts_128(bb + S_BHI + offB[i], h);
            sts_128(bb + S_BLO + offB[i], l);
        }
    }
    __syncthreads();

    for (int kc = 0; kc < NK; kc++) {
        const uint32_t buf = sbase + (uint32_t)(kc & 1) * BUF_BYTES;

        // prefetch next chunk
        if (kc + 1 < NK) {
            const float* yn = Yp + (size_t)(kc + 1) * BK;
            const float* mn_ = Mp + (size_t)(kc + 1) * BK;
#pragma unroll
            for (int i = 0; i < 4; i++) {
                ya[i] = *(const float4*)(yn + (size_t)(32 * i) * D);
                ma[i] = *(const float4*)(mn_ + (size_t)(32 * i) * D);
            }
        }

        // ---- consume current buffer ----
#pragma unroll
        for (int ks = 0; ks < 4; ks++) {
            uint32_t ah[2][4], al[2][4];
#pragma unroll
            for (int mt = 0; mt < 2; mt++) {
                const uint32_t bi = (uint32_t)((wm * 2 + mt) * 4 + ks);
#pragma unroll
                for (int reg = 0; reg < 4; reg++) {
                    uint32_t o = swzA(bi * 512 + (uint32_t)reg * 128 + (uint32_t)lane * 4);
                    ah[mt][reg] = lds_u32(buf + S_AHI + o);
                    al[mt][reg] = lds_u32(buf + S_ALO + o);
                }
            }
#pragma unroll
            for (int nt = 0; nt < 8; nt += 2) {
                uint32_t bh[2][2], bl[2][2];
#pragma unroll
                for (int u = 0; u < 2; u++) {
                    const uint32_t bi = (uint32_t)((wn * 8 + nt + u) * 4 + ks);
                    uint32_t o0 = swzB(bi * 256 + (uint32_t)lane * 4);
                    uint32_t o1 = swzB(bi * 256 + 128 + (uint32_t)lane * 4);
                    bh[u][0] = lds_u32(buf + S_BHI + o0);
                    bh[u][1] = lds_u32(buf + S_BHI + o1);
                    bl[u][0] = lds_u32(buf + S_BLO + o0);
                    bl[u][1] = lds_u32(buf + S_BLO + o1);
                }
#pragma unroll
                for (int u = 0; u < 2; u++) {
                    mma8(acc[0][nt + u], ah[0], bh[u]);
                    mma8(acc[1][nt + u], ah[1], bh[u]);
                }
#pragma unroll
                for (int u = 0; u < 2; u++) {
                    mma8(acc[0][nt + u], ah[0], bl[u]);
                    mma8(acc[1][nt + u], ah[1], bl[u]);
                }
#pragma unroll
                for (int u = 0; u < 2; u++) {
                    mma8(acc[0][nt + u], al[0], bh[u]);
                    mma8(acc[1][nt + u], al[1], bh[u]);
                }
            }
        }

        // ---- store next chunk into other buffer ----
        if (kc + 1 < NK) {
            const uint32_t bb = sbase + (uint32_t)((kc + 1) & 1) * BUF_BYTES;
#pragma unroll
            for (int i = 0; i < 4; i++) {
                uint4 h, l;
                tf32_split(ya[i].x, h.x, l.x); tf32_split(ya[i].y, h.y, l.y);
                tf32_split(ya[i].z, h.z, l.z); tf32_split(ya[i].w, h.w, l.w);
                sts_128(bb + S_AHI + offA[i], h);
                sts_128(bb + S_ALO + offA[i], l);
                tf32_split(ma[i].x, h.x, l.x); tf32_split(ma[i].y, h.y, l.y);
                tf32_split(ma[i].z, h.z, l.z); tf32_split(ma[i].w, h.w, l.w);
                sts_128(bb + S_BHI + offB[i], h);
                sts_128(bb + S_BLO + offB[i], l);
            }
        }
        __syncthreads();
    }

    // ---- fused argmin epilogue ----
    // Thread holds D rows {r0, r0+8} per mt; cols wn*64 + nt*8 + (lane&3)*2 + {0,1}
#pragma unroll
    for (int mt = 0; mt < 2; mt++) {
        unsigned long long pk0 = 0xFFFFFFFFFFFFFFFFull;
        unsigned long long pk1 = 0xFFFFFFFFFFFFFFFFull;
#pragma unroll
        for (int nt = 0; nt < 8; nt++) {
            int c0 = wn * 64 + nt * 8 + (lane & 3) * 2;
            float mn0 = sh_mn[c0], mn1 = sh_mn[c0 + 1];
            float s0 = fmaf(-2.0f, acc[mt][nt][0], mn0);
            float s1 = fmaf(-2.0f, acc[mt][nt][1], mn1);
            float s2 = fmaf(-2.0f, acc[mt][nt][2], mn0);
            float s3 = fmaf(-2.0f, acc[mt][nt][3], mn1);
            unsigned jc0 = (unsigned)(bcol + c0), jc1 = jc0 + 1;
            pk0 = umin64(pk0, ((unsigned long long)fkey(s0) << 32) | jc0);
            pk0 = umin64(pk0, ((unsigned long long)fkey(s1) << 32) | jc1);
            pk1 = umin64(pk1, ((unsigned long long)fkey(s2) << 32) | jc0);
            pk1 = umin64(pk1, ((unsigned long long)fkey(s3) << 32) | jc1);
        }
#pragma unroll
        for (int off = 1; off < 4; off <<= 1) {
            pk0 = umin64(pk0, __shfl_xor_sync(0xFFFFFFFFu, pk0, off));
            pk1 = umin64(pk1, __shfl_xor_sync(0xFFFFFFFFu, pk1, off));
        }
        if ((lane & 3) == 0) {
            int r0 = brow + wm * 32 + mt * 16 + (lane >> 2);
            atomicMin(&g_best[r0], pk0);
            atomicMin(&g_best[r0 + 8], pk1);
        }
    }
}

// ---------------------------------------------------------------------------
__global__ void winner_kernel(int B) {
    int b = blockIdx.x * blockDim.x + threadIdx.x;
    if (b < B) {
        int z = (int)(g_best[b] & 0xFFFFFFFFull);
        atomicMax(&g_winner[z], b);
    }
}

// ---------------------------------------------------------------------------
__global__ void output_kernel(const float* __restrict__ Y,
                              const float* __restrict__ M,
                              const float* __restrict__ SD,
                              float* __restrict__ out,
                              int D, int n) {
    int j = blockIdx.x;
    int w = g_winner[j];
    int D4 = D >> 2;
    const float4* mrow  = (const float4*)(M  + (size_t)j * D);
    const float4* sdrow = (const float4*)(SD + (size_t)j * D);
    float4* om = (float4*)(out + (size_t)j * D);
    float4* os = (float4*)(out + (size_t)(n + j) * D);

    if (w < 0) {
        for (int d = threadIdx.x; d < D4; d += blockDim.x) {
            om[d] = mrow[d];
            os[d] = sdrow[d];
        }
    } else {
        const float4* yrow = (const float4*)(Y + (size_t)w * D);
        for (int d = threadIdx.x; d < D4; d += blockDim.x) {
            float4 mv = mrow[d], yv = yrow[d], sv = sdrow[d];
            float4 nm, ns;
            nm.x = mv.x * EMA_OLD + yv.x * EMA_NEW;
            nm.y = mv.y * EMA_OLD + yv.y * EMA_NEW;
            nm.z = mv.z * EMA_OLD + yv.z * EMA_NEW;
            nm.w = mv.w * EMA_OLD + yv.w * EMA_NEW;
            float dx = nm.x - yv.x, dy = nm.y - yv.y,
                  dz = nm.z - yv.z, dw = nm.w - yv.w;
            ns.x = dx * dx * EMA_OLD + sv.x * EMA_NEW;
            ns.y = dy * dy * EMA_OLD + sv.y * EMA_NEW;
            ns.z = dz * dz * EMA_OLD + sv.z * EMA_NEW;
            ns.w = dw * dw * EMA_OLD + sv.w * EMA_NEW;
            om[d] = nm;
            os[d] = ns;
        }
    }
}

// ---------------------------------------------------------------------------
extern "C" void kernel_launch(void* const* d_in, const int* in_sizes, int n_in,
                              void* d_out, int out_size) {
    const float* y  = (const float*)d_in[0];
    const float* m  = (const float*)d_in[1];
    const float* sd = (const float*)d_in[2];
    (void)n_in; (void)out_size;

    const int n = in_sizes[3];            // 1024
    const int D = in_sizes[1] / n;        // 4096
    const int B = in_sizes[0] / D;        // 4096
    float* out = (float*)d_out;

    int initN = (B > n ? B : n);
    init_kernel<<<(initN + 255) / 256, 256>>>(B, n);
    mnorm_kernel<<<n, 256>>>(m, D);

    cudaFuncSetAttribute(gemm_argmin_mma,
                         cudaFuncAttributeMaxDynamicSharedMemorySize, SMEM_TOT);
    dim3 grid(n / BN, B / BM);
    gemm_argmin_mma<<<grid, 256, SMEM_TOT>>>(y, m, D);

    winner_kernel<<<(B + 255) / 256, 256>>>(B);
    output_kernel<<<n, 256>>>(y, m, sd, out, D, n);
}

// round 5
// speedup vs baseline: 1.6680x; 1.1262x over previous
#include <cuda_runtime.h>
#include <cstdint>

#define EMA_OLD 0.01f
#define EMA_NEW 0.99f

#define MAXB 4096
#define MAXN 1024

__device__ unsigned long long g_best[MAXB];   // packed (sortable_score << 32) | j
__device__ int                g_winner[MAXN];
__device__ float              g_mnorm[MAXN];

// ---------------------------------------------------------------------------
__global__ void init_kernel(int B, int n) {
    int i = blockIdx.x * blockDim.x + threadIdx.x;
    if (i < B) g_best[i] = 0xFFFFFFFFFFFFFFFFull;
    if (i < n) g_winner[i] = -1;
}

// ---------------------------------------------------------------------------
__global__ void mnorm_kernel(const float* __restrict__ M, int D) {
    int j = blockIdx.x;
    const float* row = M + (size_t)j * D;
    float s = 0.f;
    for (int d = threadIdx.x; d < D; d += blockDim.x) {
        float v = row[d];
        s = fmaf(v, v, s);
    }
    __shared__ float sh[256];
    sh[threadIdx.x] = s;
    __syncthreads();
    for (int off = 128; off > 0; off >>= 1) {
        if (threadIdx.x < off) sh[threadIdx.x] += sh[threadIdx.x + off];
        __syncthreads();
    }
    if (threadIdx.x == 0) g_mnorm[j] = sh[0];
}

// ===========================================================================
// 3xTF32 mma.sync GEMM (y @ m^T) fused with row argmin.
// CTA 128x128, BK=32, 128 threads = 4 warps in 2(M) x 2(N); warp tile 64x64.
// Smem holds f32 tiles only (split to tf32 hi/lo in registers at consume).
// cp.async 3-stage pipeline; 2 CTAs/SM.
// ===========================================================================
#define BM 128
#define BN 128
#define BK 32
#define NSTAGE 3

#define STAGE_BYTES 32768           // A(128x32 f32)=16KB + B=16KB
#define S_B 16384
#define S_MN (NSTAGE * STAGE_BYTES) // 98304
#define SMEM_TOT (S_MN + 512)

__device__ __forceinline__ uint32_t swz(uint32_t b) { return b ^ ((b >> 3) & 0x70u); }

__device__ __forceinline__ uint32_t smem_u32(const void* p) {
    uint32_t a;
    asm("{ .reg .u64 t; cvta.to.shared.u64 t, %1; cvt.u32.u64 %0, t; }" : "=r"(a) : "l"(p));
    return a;
}
// trunc-13 split: hi = top-11-mantissa part of x, lo = trunc13(x - hi)
__device__ __forceinline__ void split_t(float x, uint32_t& h, uint32_t& l) {
    uint32_t u = __float_as_uint(x);
    h = u & 0xFFFFE000u;
    float lf = x - __uint_as_float(h);
    l = __float_as_uint(lf) & 0xFFFFE000u;
}
__device__ __forceinline__ void mma8(float* d, const uint32_t* a, const uint32_t* b) {
    asm volatile(
        "mma.sync.aligned.m16n8k8.row.col.f32.tf32.tf32.f32 "
        "{%0,%1,%2,%3}, {%4,%5,%6,%7}, {%8,%9}, {%0,%1,%2,%3};"
        : "+f"(d[0]), "+f"(d[1]), "+f"(d[2]), "+f"(d[3])
        : "r"(a[0]), "r"(a[1]), "r"(a[2]), "r"(a[3]), "r"(b[0]), "r"(b[1]));
}
__device__ __forceinline__ float lds_f32(uint32_t addr) {
    float v;
    asm volatile("ld.shared.f32 %0, [%1];" : "=f"(v) : "r"(addr));
    return v;
}
#define CP_ASYNC16(dst, src) \
    asm volatile("cp.async.cg.shared.global [%0], [%1], 16;" :: "r"(dst), "l"(src))
#define CP_COMMIT() asm volatile("cp.async.commit_group;")
#define CP_WAIT1()  asm volatile("cp.async.wait_group 1;")

__device__ __forceinline__ unsigned fkey(float f) {
    unsigned u = __float_as_uint(f);
    return (u & 0x80000000u) ? ~u : (u | 0x80000000u);
}
__device__ __forceinline__ unsigned long long umin64(unsigned long long a,
                                                     unsigned long long b) {
    return a < b ? a : b;
}

__global__ __launch_bounds__(128, 2)
void gemm_argmin_mma(const float* __restrict__ Y,
                     const float* __restrict__ M,
                     int D) {
    extern __shared__ __align__(1024) char smem[];
    const uint32_t sbase = smem_u32(smem);
    const int tid  = threadIdx.x;
    const int lane = tid & 31;
    const int wid  = tid >> 5;       // 0..3
    const int wm   = wid >> 1;       // 0..1 (M)
    const int wn   = wid & 1;        // 0..1 (N)
    const int brow = blockIdx.y * BM;
    const int bcol = blockIdx.x * BN;

    float* sh_mn = (float*)(smem + S_MN);
    if (tid < 128) sh_mn[tid] = g_mnorm[bcol + tid];

    // ---- producer: 8 lines of A + 8 lines of B per thread per chunk ----
    uint32_t soff[8];
    int goff[8];
#pragma unroll
    for (int i = 0; i < 8; i++) {
        int l = tid + 128 * i;       // 0..1023
        int row = l >> 3;            // 0..127
        int kl = l & 7;              // 16B line within 128B row
        soff[i] = swz((uint32_t)(row * 128 + kl * 16));
        goff[i] = row * D + kl * 4;
    }
    const float* Yb = Y + (size_t)brow * D;
    const float* Mb = M + (size_t)bcol * D;

    float acc[4][8][4];
#pragma unroll
    for (int mt = 0; mt < 4; mt++)
#pragma unroll
        for (int nt = 0; nt < 8; nt++)
#pragma unroll
            for (int q = 0; q < 4; q++) acc[mt][nt][q] = 0.f;

    const int NK = D / BK;

    // prologue: stage chunks 0 and 1
#pragma unroll
    for (int c = 0; c < 2; c++) {
        const uint32_t sb = sbase + (uint32_t)c * STAGE_BYTES;
#pragma unroll
        for (int i = 0; i < 8; i++) {
            CP_ASYNC16(sb + soff[i], Yb + goff[i] + c * BK);
            CP_ASYNC16(sb + S_B + soff[i], Mb + goff[i] + c * BK);
        }
        CP_COMMIT();
    }

    // fragment base addresses (within a stage)
    const uint32_t arow0 = (uint32_t)(wm * 64 + (lane >> 2));
    const uint32_t nrow0 = (uint32_t)(wn * 64 + (lane >> 2));
    const uint32_t kcol0 = (uint32_t)(lane & 3);

    int stage = 0;
    for (int kc = 0; kc < NK; kc++) {
        CP_WAIT1();
        __syncthreads();

        // issue chunk kc+2 into stage (kc+2)%3
        if (kc + 2 < NK) {
            const uint32_t sb = sbase +
                (uint32_t)((stage + 2 >= NSTAGE) ? stage + 2 - NSTAGE : stage + 2) * STAGE_BYTES;
            const int ko = (kc + 2) * BK;
#pragma unroll
            for (int i = 0; i < 8; i++) {
                CP_ASYNC16(sb + soff[i], Yb + goff[i] + ko);
                CP_ASYNC16(sb + S_B + soff[i], Mb + goff[i] + ko);
            }
        }
        CP_COMMIT();

        // ---- consume current stage ----
        const uint32_t sa = sbase + (uint32_t)stage * STAGE_BYTES;
        const uint32_t sb_ = sa + S_B;
#pragma unroll
        for (int ks = 0; ks < 4; ks++) {
            const uint32_t kb = (uint32_t)(ks * 8) + kcol0;  // k index of reg0

            uint32_t ah[4][4], al[4][4];
#pragma unroll
            for (int mt = 0; mt < 4; mt++) {
                uint32_t r = arow0 + (uint32_t)(mt * 16);
                float f0 = lds_f32(sa + swz(r * 128 + kb * 4));
                float f1 = lds_f32(sa + swz((r + 8) * 128 + kb * 4));
                float f2 = lds_f32(sa + swz(r * 128 + (kb + 4) * 4));
                float f3 = lds_f32(sa + swz((r + 8) * 128 + (kb + 4) * 4));
                split_t(f0, ah[mt][0], al[mt][0]);
                split_t(f1, ah[mt][1], al[mt][1]);
                split_t(f2, ah[mt][2], al[mt][2]);
                split_t(f3, ah[mt][3], al[mt][3]);
            }
            uint32_t bh[8][2], bl[8][2];
#pragma unroll
            for (int nt = 0; nt < 8; nt++) {
                uint32_t r = nrow0 + (uint32_t)(nt * 8);
                float f0 = lds_f32(sb_ + swz(r * 128 + kb * 4));
                float f1 = lds_f32(sb_ + swz(r * 128 + (kb + 4) * 4));
                split_t(f0, bh[nt][0], bl[nt][0]);
                split_t(f1, bh[nt][1], bl[nt][1]);
            }
#pragma unroll
            for (int mt = 0; mt < 4; mt++)
#pragma unroll
                for (int nt = 0; nt < 8; nt++)
                    mma8(acc[mt][nt], ah[mt], bh[nt]);
#pragma unroll
            for (int mt = 0; mt < 4; mt++)
#pragma unroll
                for (int nt = 0; nt < 8; nt++)
                    mma8(acc[mt][nt], ah[mt], bl[nt]);
#pragma unroll
            for (int mt = 0; mt < 4; mt++)
#pragma unroll
                for (int nt = 0; nt < 8; nt++)
                    mma8(acc[mt][nt], al[mt], bh[nt]);
        }

        stage = (stage + 1 >= NSTAGE) ? 0 : stage + 1;
    }

    // ---- fused argmin epilogue ----
    // acc[mt][nt]: rows (wm*64 + mt*16 + lane>>2) + {0,8},
    //              cols wn*64 + nt*8 + (lane&3)*2 + {0,1}
#pragma unroll
    for (int mt = 0; mt < 4; mt++) {
        unsigned long long pk0 = 0xFFFFFFFFFFFFFFFFull;
        unsigned long long pk1 = 0xFFFFFFFFFFFFFFFFull;
#pragma unroll
        for (int nt = 0; nt < 8; nt++) {
            int c0 = wn * 64 + nt * 8 + (lane & 3) * 2;
            float mn0 = sh_mn[c0], mn1 = sh_mn[c0 + 1];
            float s0 = fmaf(-2.0f, acc[mt][nt][0], mn0);
            float s1 = fmaf(-2.0f, acc[mt][nt][1], mn1);
            float s2 = fmaf(-2.0f, acc[mt][nt][2], mn0);
            float s3 = fmaf(-2.0f, acc[mt][nt][3], mn1);
            unsigned jc0 = (unsigned)(bcol + c0), jc1 = jc0 + 1;
            pk0 = umin64(pk0, ((unsigned long long)fkey(s0) << 32) | jc0);
            pk0 = umin64(pk0, ((unsigned long long)fkey(s1) << 32) | jc1);
            pk1 = umin64(pk1, ((unsigned long long)fkey(s2) << 32) | jc0);
            pk1 = umin64(pk1, ((unsigned long long)fkey(s3) << 32) | jc1);
        }
#pragma unroll
        for (int off = 1; off < 4; off <<= 1) {
            pk0 = umin64(pk0, __shfl_xor_sync(0xFFFFFFFFu, pk0, off));
            pk1 = umin64(pk1, __shfl_xor_sync(0xFFFFFFFFu, pk1, off));
        }
        if ((lane & 3) == 0) {
            int r0 = brow + wm * 64 + mt * 16 + (lane >> 2);
            atomicMin(&g_best[r0], pk0);
            atomicMin(&g_best[r0 + 8], pk1);
        }
    }
}

// ---------------------------------------------------------------------------
__global__ void winner_kernel(int B) {
    int b = blockIdx.x * blockDim.x + threadIdx.x;
    if (b < B) {
        int z = (int)(g_best[b] & 0xFFFFFFFFull);
        atomicMax(&g_winner[z], b);
    }
}

// ---------------------------------------------------------------------------
__global__ void output_kernel(const float* __restrict__ Y,
                              const float* __restrict__ M,
                              const float* __restrict__ SD,
                              float* __restrict__ out,
                              int D, int n) {
    int j = blockIdx.x;
    int w = g_winner[j];
    int D4 = D >> 2;
    const float4* mrow  = (const float4*)(M  + (size_t)j * D);
    const float4* sdrow = (const float4*)(SD + (size_t)j * D);
    float4* om = (float4*)(out + (size_t)j * D);
    float4* os = (float4*)(out + (size_t)(n + j) * D);

    if (w < 0) {
        for (int d = threadIdx.x; d < D4; d += blockDim.x) {
            om[d] = mrow[d];
            os[d] = sdrow[d];
        }
    } else {
        const float4* yrow = (const float4*)(Y + (size_t)w * D);
        for (int d = threadIdx.x; d < D4; d += blockDim.x) {
            float4 mv = mrow[d], yv = yrow[d], sv = sdrow[d];
            float4 nm, ns;
            nm.x = mv.x * EMA_OLD + yv.x * EMA_NEW;
            nm.y = mv.y * EMA_OLD + yv.y * EMA_NEW;
            nm.z = mv.z * EMA_OLD + yv.z * EMA_NEW;
            nm.w = mv.w * EMA_OLD + yv.w * EMA_NEW;
            float dx = nm.x - yv.x, dy = nm.y - yv.y,
                  dz = nm.z - yv.z, dw = nm.w - yv.w;
            ns.x = dx * dx * EMA_OLD + sv.x * EMA_NEW;
            ns.y = dy * dy * EMA_OLD + sv.y * EMA_NEW;
            ns.z = dz * dz * EMA_OLD + sv.z * EMA_NEW;
            ns.w = dw * dw * EMA_OLD + sv.w * EMA_NEW;
            om[d] = nm;
            os[d] = ns;
        }
    }
}

// ---------------------------------------------------------------------------
extern "C" void kernel_launch(void* const* d_in, const int* in_sizes, int n_in,
                              void* d_out, int out_size) {
    const float* y  = (const float*)d_in[0];
    const float* m  = (const float*)d_in[1];
    const float* sd = (const float*)d_in[2];
    (void)n_in; (void)out_size;

    const int n = in_sizes[3];            // 1024
    const int D = in_sizes[1] / n;        // 4096
    const int B = in_sizes[0] / D;        // 4096
    float* out = (float*)d_out;

    int initN = (B > n ? B : n);
    init_kernel<<<(initN + 255) / 256, 256>>>(B, n);
    mnorm_kernel<<<n, 256>>>(m, D);

    cudaFuncSetAttribute(gemm_argmin_mma,
                         cudaFuncAttributeMaxDynamicSharedMemorySize, SMEM_TOT);
    dim3 grid(n / BN, B / BM);
    gemm_argmin_mma<<<grid, 128, SMEM_TOT>>>(y, m, D);

    winner_kernel<<<(B + 255) / 256, 256>>>(B);
    output_kernel<<<n, 256>>>(y, m, sd, out, D, n);
}

// round 6
// speedup vs baseline: 3.4311x; 2.0570x over previous
#include <cuda_runtime.h>
#include <cstdint>

#define EMA_OLD 0.01f
#define EMA_NEW 0.99f

#define MAXB 4096
#define MAXN 1024

__device__ float g_d2[(size_t)MAXB * MAXN];   // approx distances (16.8 MB)
__device__ int   g_winner[MAXN];
__device__ float g_mnorm[MAXN];

// ---------------------------------------------------------------------------
__global__ void init_kernel(int n) {
    int i = blockIdx.x * blockDim.x + threadIdx.x;
    if (i < n) g_winner[i] = -1;
}

// ---------------------------------------------------------------------------
__global__ void mnorm_kernel(const float* __restrict__ M, int D) {
    int j = blockIdx.x;
    const float* row = M + (size_t)j * D;
    float s = 0.f;
    for (int d = threadIdx.x; d < D; d += blockDim.x) {
        float v = row[d];
        s = fmaf(v, v, s);
    }
    __shared__ float sh[256];
    sh[threadIdx.x] = s;
    __syncthreads();
    for (int off = 128; off > 0; off >>= 1) {
        if (threadIdx.x < off) sh[threadIdx.x] += sh[threadIdx.x + off];
        __syncthreads();
    }
    if (threadIdx.x == 0) g_mnorm[j] = sh[0];
}

// ===========================================================================
// Phase 1: single-term truncated-tf32 mma.sync GEMM (y @ m^T), writes d2.
// CTA 128x128, BK=32, 128 threads = 4 warps (2M x 2N); warp tile 64x64.
// cp.async 3-stage pipeline, f32 tiles in smem, trunc-mask at consume.
// ===========================================================================
#define BM 128
#define BN 128
#define BK 32
#define NSTAGE 3

#define STAGE_BYTES 32768
#define S_B 16384
#define S_MN (NSTAGE * STAGE_BYTES)
#define SMEM_TOT (S_MN + 512)

__device__ __forceinline__ uint32_t swz(uint32_t b) { return b ^ ((b >> 3) & 0x70u); }

__device__ __forceinline__ uint32_t smem_u32(const void* p) {
    uint32_t a;
    asm("{ .reg .u64 t; cvta.to.shared.u64 t, %1; cvt.u32.u64 %0, t; }" : "=r"(a) : "l"(p));
    return a;
}
__device__ __forceinline__ void mma8(float* d, const uint32_t* a, const uint32_t* b) {
    asm volatile(
        "mma.sync.aligned.m16n8k8.row.col.f32.tf32.tf32.f32 "
        "{%0,%1,%2,%3}, {%4,%5,%6,%7}, {%8,%9}, {%0,%1,%2,%3};"
        : "+f"(d[0]), "+f"(d[1]), "+f"(d[2]), "+f"(d[3])
        : "r"(a[0]), "r"(a[1]), "r"(a[2]), "r"(a[3]), "r"(b[0]), "r"(b[1]));
}
__device__ __forceinline__ uint32_t lds_t(uint32_t addr) {
    uint32_t v;
    asm volatile("ld.shared.b32 %0, [%1];" : "=r"(v) : "r"(addr));
    return v & 0xFFFFE000u;   // truncate to tf32 (10 mantissa bits)
}
#define CP_ASYNC16(dst, src) \
    asm volatile("cp.async.cg.shared.global [%0], [%1], 16;" :: "r"(dst), "l"(src))
#define CP_COMMIT() asm volatile("cp.async.commit_group;")
#define CP_WAIT1()  asm volatile("cp.async.wait_group 1;")

__device__ __forceinline__ unsigned fkey(float f) {
    unsigned u = __float_as_uint(f);
    return (u & 0x80000000u) ? ~u : (u | 0x80000000u);
}

__global__ __launch_bounds__(128, 2)
void gemm_d2_mma(const float* __restrict__ Y,
                 const float* __restrict__ M,
                 int D, int n) {
    extern __shared__ __align__(1024) char smem[];
    const uint32_t sbase = smem_u32(smem);
    const int tid  = threadIdx.x;
    const int lane = tid & 31;
    const int wid  = tid >> 5;
    const int wm   = wid >> 1;
    const int wn   = wid & 1;
    const int brow = blockIdx.y * BM;
    const int bcol = blockIdx.x * BN;

    float* sh_mn = (float*)(smem + S_MN);
    if (tid < 128) sh_mn[tid] = g_mnorm[bcol + tid];

    uint32_t soff[8];
    int goff[8];
#pragma unroll
    for (int i = 0; i < 8; i++) {
        int l = tid + 128 * i;
        int row = l >> 3;
        int kl = l & 7;
        soff[i] = swz((uint32_t)(row * 128 + kl * 16));
        goff[i] = row * D + kl * 4;
    }
    const float* Yb = Y + (size_t)brow * D;
    const float* Mb = M + (size_t)bcol * D;

    float acc[4][8][4];
#pragma unroll
    for (int mt = 0; mt < 4; mt++)
#pragma unroll
        for (int nt = 0; nt < 8; nt++)
#pragma unroll
            for (int q = 0; q < 4; q++) acc[mt][nt][q] = 0.f;

    const int NK = D / BK;

#pragma unroll
    for (int c = 0; c < 2; c++) {
        const uint32_t sb = sbase + (uint32_t)c * STAGE_BYTES;
#pragma unroll
        for (int i = 0; i < 8; i++) {
            CP_ASYNC16(sb + soff[i], Yb + goff[i] + c * BK);
            CP_ASYNC16(sb + S_B + soff[i], Mb + goff[i] + c * BK);
        }
        CP_COMMIT();
    }

    const uint32_t arow0 = (uint32_t)(wm * 64 + (lane >> 2));
    const uint32_t nrow0 = (uint32_t)(wn * 64 + (lane >> 2));
    const uint32_t kcol0 = (uint32_t)(lane & 3);

    int stage = 0;
    for (int kc = 0; kc < NK; kc++) {
        CP_WAIT1();
        __syncthreads();

        if (kc + 2 < NK) {
            const uint32_t sb = sbase +
                (uint32_t)((stage + 2 >= NSTAGE) ? stage + 2 - NSTAGE : stage + 2) * STAGE_BYTES;
            const int ko = (kc + 2) * BK;
#pragma unroll
            for (int i = 0; i < 8; i++) {
                CP_ASYNC16(sb + soff[i], Yb + goff[i] + ko);
                CP_ASYNC16(sb + S_B + soff[i], Mb + goff[i] + ko);
            }
        }
        CP_COMMIT();

        const uint32_t sa = sbase + (uint32_t)stage * STAGE_BYTES;
        const uint32_t sb_ = sa + S_B;
#pragma unroll
        for (int ks = 0; ks < 4; ks++) {
            const uint32_t kb = (uint32_t)(ks * 8) + kcol0;

            uint32_t ah[4][4];
#pragma unroll
            for (int mt = 0; mt < 4; mt++) {
                uint32_t r = arow0 + (uint32_t)(mt * 16);
                ah[mt][0] = lds_t(sa + swz(r * 128 + kb * 4));
                ah[mt][1] = lds_t(sa + swz((r + 8) * 128 + kb * 4));
                ah[mt][2] = lds_t(sa + swz(r * 128 + (kb + 4) * 4));
                ah[mt][3] = lds_t(sa + swz((r + 8) * 128 + (kb + 4) * 4));
            }
            uint32_t bh[8][2];
#pragma unroll
            for (int nt = 0; nt < 8; nt++) {
                uint32_t r = nrow0 + (uint32_t)(nt * 8);
                bh[nt][0] = lds_t(sb_ + swz(r * 128 + kb * 4));
                bh[nt][1] = lds_t(sb_ + swz(r * 128 + (kb + 4) * 4));
            }
#pragma unroll
            for (int mt = 0; mt < 4; mt++)
#pragma unroll
                for (int nt = 0; nt < 8; nt++)
                    mma8(acc[mt][nt], ah[mt], bh[nt]);
        }

        stage = (stage + 1 >= NSTAGE) ? 0 : stage + 1;
    }

    // ---- epilogue: d2 = ||m||^2 - 2*dot, store to g_d2 ----
#pragma unroll
    for (int mt = 0; mt < 4; mt++) {
        int r0 = brow + wm * 64 + mt * 16 + (lane >> 2);
#pragma unroll
        for (int nt = 0; nt < 8; nt++) {
            int cl = wn * 64 + nt * 8 + (lane & 3) * 2;
            float mn0 = sh_mn[cl], mn1 = sh_mn[cl + 1];
            float2 p0, p1;
            p0.x = fmaf(-2.0f, acc[mt][nt][0], mn0);
            p0.y = fmaf(-2.0f, acc[mt][nt][1], mn1);
            p1.x = fmaf(-2.0f, acc[mt][nt][2], mn0);
            p1.y = fmaf(-2.0f, acc[mt][nt][3], mn1);
            size_t base = (size_t)r0 * n + (bcol + cl);
            *(float2*)&g_d2[base] = p0;
            *(float2*)&g_d2[base + (size_t)8 * n] = p1;
        }
    }
}

// ===========================================================================
// Phase 2: per-row min + candidate set + exact fp32 rescoring if ambiguous.
// ===========================================================================
#define SEL_EPS 8.0f

__global__ __launch_bounds__(128)
void select_kernel(const float* __restrict__ Y,
                   const float* __restrict__ M,
                   int D, int n) {
    const int b = blockIdx.x;
    const int tid = threadIdx.x;
    const int lane = tid & 31;
    const int wid = tid >> 5;
    const float* row = g_d2 + (size_t)b * n;

    __shared__ float swarp[4];
    __shared__ int cand[64];
    __shared__ int cnt;
    __shared__ unsigned long long bestpk;
    if (tid == 0) { cnt = 0; bestpk = 0xFFFFFFFFFFFFFFFFull; }

    float lmin = 3.4e38f;
    for (int j = tid; j < n; j += 128) lmin = fminf(lmin, row[j]);
#pragma unroll
    for (int off = 16; off > 0; off >>= 1)
        lmin = fminf(lmin, __shfl_xor_sync(0xFFFFFFFFu, lmin, off));
    if (lane == 0) swarp[wid] = lmin;
    __syncthreads();
    float bmin = fminf(fminf(swarp[0], swarp[1]), fminf(swarp[2], swarp[3]));

    float thr = bmin + SEL_EPS;
    for (int j = tid; j < n; j += 128) {
        if (row[j] <= thr) {
            int i = atomicAdd(&cnt, 1);
            if (i < 64) cand[i] = j;
        }
    }
    __syncthreads();
    int c = cnt < 64 ? cnt : 64;

    int bestj;
    if (c <= 1) {
        bestj = cand[0];
    } else {
        // exact fp32 rescoring of the candidates
        const float* yrow = Y + (size_t)b * D;
        for (int i = 0; i < c; i++) {
            int j = cand[i];
            const float* mrow = M + (size_t)j * D;
            float p = 0.f;
            for (int d = tid; d < D; d += 128)
                p = fmaf(yrow[d], mrow[d], p);
#pragma unroll
            for (int off = 16; off > 0; off >>= 1)
                p += __shfl_xor_sync(0xFFFFFFFFu, p, off);
            if (lane == 0) swarp[wid] = p;
            __syncthreads();
            if (tid == 0) {
                float dot = (swarp[0] + swarp[1]) + (swarp[2] + swarp[3]);
                float s = fmaf(-2.0f, dot, g_mnorm[j]);
                unsigned long long pk =
                    ((unsigned long long)fkey(s) << 32) | (unsigned)j;
                if (pk < bestpk) bestpk = pk;
            }
            __syncthreads();
        }
        bestj = (int)(bestpk & 0xFFFFFFFFull);
    }

    if (tid == 0) atomicMax(&g_winner[bestj], b);
}

// ---------------------------------------------------------------------------
__global__ void output_kernel(const float* __restrict__ Y,
                              const float* __restrict__ M,
                              const float* __restrict__ SD,
                              float* __restrict__ out,
                              int D, int n) {
    int j = blockIdx.x;
    int w = g_winner[j];
    int D4 = D >> 2;
    const float4* mrow  = (const float4*)(M  + (size_t)j * D);
    const float4* sdrow = (const float4*)(SD + (size_t)j * D);
    float4* om = (float4*)(out + (size_t)j * D);
    float4* os = (float4*)(out + (size_t)(n + j) * D);

    if (w < 0) {
        for (int d = threadIdx.x; d < D4; d += blockDim.x) {
            om[d] = mrow[d];
            os[d] = sdrow[d];
        }
    } else {
        const float4* yrow = (const float4*)(Y + (size_t)w * D);
        for (int d = threadIdx.x; d < D4; d += blockDim.x) {
            float4 mv = mrow[d], yv = yrow[d], sv = sdrow[d];
            float4 nm, ns;
            nm.x = mv.x * EMA_OLD + yv.x * EMA_NEW;
            nm.y = mv.y * EMA_OLD + yv.y * EMA_NEW;
            nm.z = mv.z * EMA_OLD + yv.z * EMA_NEW;
            nm.w = mv.w * EMA_OLD + yv.w * EMA_NEW;
            float dx = nm.x - yv.x, dy = nm.y - yv.y,
                  dz = nm.z - yv.z, dw = nm.w - yv.w;
            ns.x = dx * dx * EMA_OLD + sv.x * EMA_NEW;
            ns.y = dy * dy * EMA_OLD + sv.y * EMA_NEW;
            ns.z = dz * dz * EMA_OLD + sv.z * EMA_NEW;
            ns.w = dw * dw * EMA_OLD + sv.w * EMA_NEW;
            om[d] = nm;
            os[d] = ns;
        }
    }
}

// ---------------------------------------------------------------------------
extern "C" void kernel_launch(void* const* d_in, const int* in_sizes, int n_in,
                              void* d_out, int out_size) {
    const float* y  = (const float*)d_in[0];
    const float* m  = (const float*)d_in[1];
    const float* sd = (const float*)d_in[2];
    (void)n_in; (void)out_size;

    const int n = in_sizes[3];            // 1024
    const int D = in_sizes[1] / n;        // 4096
    const int B = in_sizes[0] / D;        // 4096
    float* out = (float*)d_out;

    init_kernel<<<(n + 255) / 256, 256>>>(n);
    mnorm_kernel<<<n, 256>>>(m, D);

    cudaFuncSetAttribute(gemm_d2_mma,
                         cudaFuncAttributeMaxDynamicSharedMemorySize, SMEM_TOT);
    dim3 grid(n / BN, B / BM);
    gemm_d2_mma<<<grid, 128, SMEM_TOT>>>(y, m, D, n);

    select_kernel<<<B, 128>>>(y, m, D, n);
    output_kernel<<<n, 256>>>(y, m, sd, out, D, n);
}

// round 7
// speedup vs baseline: 3.6283x; 1.0575x over previous
#include <cuda_runtime.h>
#include <cstdint>

#define EMA_OLD 0.01f
#define EMA_NEW 0.99f

#define MAXB 4096
#define MAXN 1024

__device__ float              g_d2[(size_t)MAXB * MAXN];  // approx distances
__device__ unsigned long long g_best[MAXB];               // packed (fkey(score)<<32)|j
__device__ int                g_winner[MAXN];
__device__ float              g_mnorm[MAXN];

// ---------------------------------------------------------------------------
__global__ void init_kernel(int B, int n) {
    int i = blockIdx.x * blockDim.x + threadIdx.x;
    if (i < B) g_best[i] = 0xFFFFFFFFFFFFFFFFull;
    if (i < n) g_winner[i] = -1;
}

// ---------------------------------------------------------------------------
__global__ void mnorm_kernel(const float* __restrict__ M, int D) {
    int j = blockIdx.x;
    const float* row = M + (size_t)j * D;
    float s = 0.f;
    for (int d = threadIdx.x; d < D; d += blockDim.x) {
        float v = row[d];
        s = fmaf(v, v, s);
    }
    __shared__ float sh[256];
    sh[threadIdx.x] = s;
    __syncthreads();
    for (int off = 128; off > 0; off >>= 1) {
        if (threadIdx.x < off) sh[threadIdx.x] += sh[threadIdx.x + off];
        __syncthreads();
    }
    if (threadIdx.x == 0) g_mnorm[j] = sh[0];
}

// ===========================================================================
// Phase 1: tf32 mma.sync GEMM (y @ m^T); writes d2 AND fused approx argmin.
// CTA 128x128, BK=32, 128 threads = 4 warps (2M x 2N); warp tile 64x64.
// ===========================================================================
#define BM 128
#define BN 128
#define BK 32
#define NSTAGE 3

#define STAGE_BYTES 32768
#define S_B 16384
#define S_MN (NSTAGE * STAGE_BYTES)
#define SMEM_TOT (S_MN + 512)

__device__ __forceinline__ uint32_t swz(uint32_t b) { return b ^ ((b >> 3) & 0x70u); }

__device__ __forceinline__ uint32_t smem_u32(const void* p) {
    uint32_t a;
    asm("{ .reg .u64 t; cvta.to.shared.u64 t, %1; cvt.u32.u64 %0, t; }" : "=r"(a) : "l"(p));
    return a;
}
__device__ __forceinline__ void mma8(float* d, const uint32_t* a, const uint32_t* b) {
    asm volatile(
        "mma.sync.aligned.m16n8k8.row.col.f32.tf32.tf32.f32 "
        "{%0,%1,%2,%3}, {%4,%5,%6,%7}, {%8,%9}, {%0,%1,%2,%3};"
        : "+f"(d[0]), "+f"(d[1]), "+f"(d[2]), "+f"(d[3])
        : "r"(a[0]), "r"(a[1]), "r"(a[2]), "r"(a[3]), "r"(b[0]), "r"(b[1]));
}
__device__ __forceinline__ uint32_t lds_u32(uint32_t addr) {
    uint32_t v;
    asm volatile("ld.shared.b32 %0, [%1];" : "=r"(v) : "r"(addr));
    return v;    // raw f32 bits; HW reads tf32 precision from them
}
#define CP_ASYNC16(dst, src) \
    asm volatile("cp.async.cg.shared.global [%0], [%1], 16;" :: "r"(dst), "l"(src))
#define CP_COMMIT() asm volatile("cp.async.commit_group;")
#define CP_WAIT1()  asm volatile("cp.async.wait_group 1;")

__device__ __forceinline__ unsigned fkey(float f) {
    unsigned u = __float_as_uint(f);
    return (u & 0x80000000u) ? ~u : (u | 0x80000000u);
}
__device__ __forceinline__ float unfkey(unsigned k) {
    unsigned u = (k & 0x80000000u) ? (k ^ 0x80000000u) : ~k;
    return __uint_as_float(u);
}
__device__ __forceinline__ unsigned long long umin64(unsigned long long a,
                                                     unsigned long long b) {
    return a < b ? a : b;
}

__global__ __launch_bounds__(128, 2)
void gemm_d2_mma(const float* __restrict__ Y,
                 const float* __restrict__ M,
                 int D, int n) {
    extern __shared__ __align__(1024) char smem[];
    const uint32_t sbase = smem_u32(smem);
    const int tid  = threadIdx.x;
    const int lane = tid & 31;
    const int wid  = tid >> 5;
    const int wm   = wid >> 1;
    const int wn   = wid & 1;
    const int brow = blockIdx.y * BM;
    const int bcol = blockIdx.x * BN;

    float* sh_mn = (float*)(smem + S_MN);
    if (tid < 128) sh_mn[tid] = g_mnorm[bcol + tid];

    uint32_t soff[8];
    int goff[8];
#pragma unroll
    for (int i = 0; i < 8; i++) {
        int l = tid + 128 * i;
        int row = l >> 3;
        int kl = l & 7;
        soff[i] = swz((uint32_t)(row * 128 + kl * 16));
        goff[i] = row * D + kl * 4;
    }
    const float* Yb = Y + (size_t)brow * D;
    const float* Mb = M + (size_t)bcol * D;

    float acc[4][8][4];
#pragma unroll
    for (int mt = 0; mt < 4; mt++)
#pragma unroll
        for (int nt = 0; nt < 8; nt++)
#pragma unroll
            for (int q = 0; q < 4; q++) acc[mt][nt][q] = 0.f;

    const int NK = D / BK;

#pragma unroll
    for (int c = 0; c < 2; c++) {
        const uint32_t sb = sbase + (uint32_t)c * STAGE_BYTES;
#pragma unroll
        for (int i = 0; i < 8; i++) {
            CP_ASYNC16(sb + soff[i], Yb + goff[i] + c * BK);
            CP_ASYNC16(sb + S_B + soff[i], Mb + goff[i] + c * BK);
        }
        CP_COMMIT();
    }

    const uint32_t arow0 = (uint32_t)(wm * 64 + (lane >> 2));
    const uint32_t nrow0 = (uint32_t)(wn * 64 + (lane >> 2));
    const uint32_t kcol0 = (uint32_t)(lane & 3);

    int stage = 0;
    for (int kc = 0; kc < NK; kc++) {
        CP_WAIT1();
        __syncthreads();

        if (kc + 2 < NK) {
            const uint32_t sb = sbase +
                (uint32_t)((stage + 2 >= NSTAGE) ? stage + 2 - NSTAGE : stage + 2) * STAGE_BYTES;
            const int ko = (kc + 2) * BK;
#pragma unroll
            for (int i = 0; i < 8; i++) {
                CP_ASYNC16(sb + soff[i], Yb + goff[i] + ko);
                CP_ASYNC16(sb + S_B + soff[i], Mb + goff[i] + ko);
            }
        }
        CP_COMMIT();

        const uint32_t sa = sbase + (uint32_t)stage * STAGE_BYTES;
        const uint32_t sb_ = sa + S_B;
#pragma unroll
        for (int ks = 0; ks < 4; ks++) {
            const uint32_t kb = (uint32_t)(ks * 8) + kcol0;

            uint32_t ah[4][4];
#pragma unroll
            for (int mt = 0; mt < 4; mt++) {
                uint32_t r = arow0 + (uint32_t)(mt * 16);
                ah[mt][0] = lds_u32(sa + swz(r * 128 + kb * 4));
                ah[mt][1] = lds_u32(sa + swz((r + 8) * 128 + kb * 4));
                ah[mt][2] = lds_u32(sa + swz(r * 128 + (kb + 4) * 4));
                ah[mt][3] = lds_u32(sa + swz((r + 8) * 128 + (kb + 4) * 4));
            }
            uint32_t bh[8][2];
#pragma unroll
            for (int nt = 0; nt < 8; nt++) {
                uint32_t r = nrow0 + (uint32_t)(nt * 8);
                bh[nt][0] = lds_u32(sb_ + swz(r * 128 + kb * 4));
                bh[nt][1] = lds_u32(sb_ + swz(r * 128 + (kb + 4) * 4));
            }
#pragma unroll
            for (int mt = 0; mt < 4; mt++)
#pragma unroll
                for (int nt = 0; nt < 8; nt++)
                    mma8(acc[mt][nt], ah[mt], bh[nt]);
        }

        stage = (stage + 1 >= NSTAGE) ? 0 : stage + 1;
    }

    // ---- epilogue: d2 = ||m||^2 - 2*dot, store + fused approx argmin ----
#pragma unroll
    for (int mt = 0; mt < 4; mt++) {
        int r0 = brow + wm * 64 + mt * 16 + (lane >> 2);
        unsigned long long pk0 = 0xFFFFFFFFFFFFFFFFull;
        unsigned long long pk1 = 0xFFFFFFFFFFFFFFFFull;
#pragma unroll
        for (int nt = 0; nt < 8; nt++) {
            int cl = wn * 64 + nt * 8 + (lane & 3) * 2;
            float mn0 = sh_mn[cl], mn1 = sh_mn[cl + 1];
            float2 p0, p1;
            p0.x = fmaf(-2.0f, acc[mt][nt][0], mn0);
            p0.y = fmaf(-2.0f, acc[mt][nt][1], mn1);
            p1.x = fmaf(-2.0f, acc[mt][nt][2], mn0);
            p1.y = fmaf(-2.0f, acc[mt][nt][3], mn1);
            size_t base = (size_t)r0 * n + (bcol + cl);
            *(float2*)&g_d2[base] = p0;
            *(float2*)&g_d2[base + (size_t)8 * n] = p1;
            unsigned j0 = (unsigned)(bcol + cl), j1 = j0 + 1;
            pk0 = umin64(pk0, ((unsigned long long)fkey(p0.x) << 32) | j0);
            pk0 = umin64(pk0, ((unsigned long long)fkey(p0.y) << 32) | j1);
            pk1 = umin64(pk1, ((unsigned long long)fkey(p1.x) << 32) | j0);
            pk1 = umin64(pk1, ((unsigned long long)fkey(p1.y) << 32) | j1);
        }
#pragma unroll
        for (int off = 1; off < 4; off <<= 1) {
            pk0 = umin64(pk0, __shfl_xor_sync(0xFFFFFFFFu, pk0, off));
            pk1 = umin64(pk1, __shfl_xor_sync(0xFFFFFFFFu, pk1, off));
        }
        if ((lane & 3) == 0) {
            atomicMin(&g_best[r0], pk0);
            atomicMin(&g_best[r0 + 8], pk1);
        }
    }
}

// ===========================================================================
// Phase 2: warp-per-row candidate scan; exact fp32 rescore only if ambiguous.
// ===========================================================================
#define SEL_EPS 8.0f
#define SEL_WPB 8          // warps per block
#define MAXCAND 16

__global__ __launch_bounds__(SEL_WPB * 32)
void select_kernel(const float* __restrict__ Y,
                   const float* __restrict__ M,
                   int D, int n, int B) {
    const int lane = threadIdx.x & 31;
    const int wloc = threadIdx.x >> 5;
    const int b = blockIdx.x * SEL_WPB + wloc;
    if (b >= B) return;

    __shared__ int scand[SEL_WPB][MAXCAND];
    __shared__ int scnt[SEL_WPB];
    if (lane == 0) scnt[wloc] = 0;
    __syncwarp();

    const unsigned long long bk = g_best[b];
    const int jstar = (int)(bk & 0xFFFFFFFFull);
    const float thr = unfkey((unsigned)(bk >> 32)) + SEL_EPS;

    const float4* row = (const float4*)(g_d2 + (size_t)b * n);
    int total = 0;
    for (int i = lane; i < (n >> 2); i += 32) {
        float4 v = row[i];
        int c = (v.x <= thr) + (v.y <= thr) + (v.z <= thr) + (v.w <= thr);
        if (c) {
            int base = atomicAdd(&scnt[wloc], c);
            int idx = 4 * i;
            if (v.x <= thr && base < MAXCAND) scand[wloc][base++] = idx;
            if (v.y <= thr && base < MAXCAND) scand[wloc][base++] = idx + 1;
            if (v.z <= thr && base < MAXCAND) scand[wloc][base++] = idx + 2;
            if (v.w <= thr && base < MAXCAND) scand[wloc][base++] = idx + 3;
        }
        total += c;
    }
#pragma unroll
    for (int off = 16; off > 0; off >>= 1)
        total += __shfl_xor_sync(0xFFFFFFFFu, total, off);
    __syncwarp();

    int bestj = jstar;
    if (total > 1) {
        int c = scnt[wloc] < MAXCAND ? scnt[wloc] : MAXCAND;
        const float* yrow = Y + (size_t)b * D;
        unsigned long long best = 0xFFFFFFFFFFFFFFFFull;
        for (int i = 0; i < c; i++) {
            int j = scand[wloc][i];
            const float* mrow = M + (size_t)j * D;
            float p = 0.f;
            for (int d = lane * 4; d < D; d += 128) {
                float4 yv = *(const float4*)(yrow + d);
                float4 mv = *(const float4*)(mrow + d);
                p = fmaf(yv.x, mv.x, p);
                p = fmaf(yv.y, mv.y, p);
                p = fmaf(yv.z, mv.z, p);
                p = fmaf(yv.w, mv.w, p);
            }
#pragma unroll
            for (int off = 16; off > 0; off >>= 1)
                p += __shfl_xor_sync(0xFFFFFFFFu, p, off);
            float s = fmaf(-2.0f, p, g_mnorm[j]);
            unsigned long long pk =
                ((unsigned long long)fkey(s) << 32) | (unsigned)j;
            best = best < pk ? best : pk;
        }
        bestj = (int)(best & 0xFFFFFFFFull);
    }

    if (lane == 0) atomicMax(&g_winner[bestj], b);
}

// ---------------------------------------------------------------------------
__global__ void output_kernel(const float* __restrict__ Y,
                              const float* __restrict__ M,
                              const float* __restrict__ SD,
                              float* __restrict__ out,
                              int D, int n) {
    int j = blockIdx.x;
    int w = g_winner[j];
    int D4 = D >> 2;
    const float4* mrow  = (const float4*)(M  + (size_t)j * D);
    const float4* sdrow = (const float4*)(SD + (size_t)j * D);
    float4* om = (float4*)(out + (size_t)j * D);
    float4* os = (float4*)(out + (size_t)(n + j) * D);

    if (w < 0) {
        for (int d = threadIdx.x; d < D4; d += blockDim.x) {
            om[d] = mrow[d];
            os[d] = sdrow[d];
        }
    } else {
        const float4* yrow = (const float4*)(Y + (size_t)w * D);
        for (int d = threadIdx.x; d < D4; d += blockDim.x) {
            float4 mv = mrow[d], yv = yrow[d], sv = sdrow[d];
            float4 nm, ns;
            nm.x = mv.x * EMA_OLD + yv.x * EMA_NEW;
            nm.y = mv.y * EMA_OLD + yv.y * EMA_NEW;
            nm.z = mv.z * EMA_OLD + yv.z * EMA_NEW;
            nm.w = mv.w * EMA_OLD + yv.w * EMA_NEW;
            float dx = nm.x - yv.x, dy = nm.y - yv.y,
                  dz = nm.z - yv.z, dw = nm.w - yv.w;
            ns.x = dx * dx * EMA_OLD + sv.x * EMA_NEW;
            ns.y = dy * dy * EMA_OLD + sv.y * EMA_NEW;
            ns.z = dz * dz * EMA_OLD + sv.z * EMA_NEW;
            ns.w = dw * dw * EMA_OLD + sv.w * EMA_NEW;
            om[d] = nm;
            os[d] = ns;
        }
    }
}

// ---------------------------------------------------------------------------
extern "C" void kernel_launch(void* const* d_in, const int* in_sizes, int n_in,
                              void* d_out, int out_size) {
    const float* y  = (const float*)d_in[0];
    const float* m  = (const float*)d_in[1];
    const float* sd = (const float*)d_in[2];
    (void)n_in; (void)out_size;

    const int n = in_sizes[3];            // 1024
    const int D = in_sizes[1] / n;        // 4096
    const int B = in_sizes[0] / D;        // 4096
    float* out = (float*)d_out;

    int initN = (B > n ? B : n);
    init_kernel<<<(initN + 255) / 256, 256>>>(B, n);
    mnorm_kernel<<<n, 256>>>(m, D);

    cudaFuncSetAttribute(gemm_d2_mma,
                         cudaFuncAttributeMaxDynamicSharedMemorySize, SMEM_TOT);
    dim3 grid(n / BN, B / BM);
    gemm_d2_mma<<<grid, 128, SMEM_TOT>>>(y, m, D, n);

    select_kernel<<<(B + SEL_WPB - 1) / SEL_WPB, SEL_WPB * 32>>>(y, m, D, n, B);
    output_kernel<<<n, 256>>>(y, m, sd, out, D, n);
}